// round 2
// baseline (speedup 1.0000x reference)
#include <cuda_runtime.h>
#include <cstdint>

// Spatial RNN, 4 directions, R=8 chain steps, C=64 channels.
// x: (8,192,192,64) fp32; W_*: (64,64); out: (8,192,192,256)
// One CTA per scan line. Per line: 2 directions x 8 chained [192,64]x[64,64]
// GEMMs (mma.sync tf32) with relu + 1-pixel shift between steps.
//
// R2 optimizations vs R1:
//  - B fragments hoisted to registers (loaded from gmem once per direction)
//  - state buffers use a permuted column layout -> A fragments load as LDS.64
//  - tf32 rounding applied once at store time (not per A-load)
//  - 3 buffers: Xbuf (persistent x) + P0/P1 ping-pong, zero guard rows
//    (no boundary predicates, 1 barrier/step, no x reload for dir 2)
//  - final step skips state stores; epilogue reads x from smem

#define LINE 192
#define RSTEPS 8
#define LSTR 68                 // padded row stride (floats)
#define BROWS 194               // 192 rows + zero guard row on each side
#define BUFSZ (BROWS * LSTR)    // 13192 floats
#define SMEM_BYTES (3 * BUFSZ * 4)   // 158304 bytes
#define NLINES_H 1536

__device__ __forceinline__ float tf32r(float v) {
    float r;
    asm("cvt.rna.tf32.f32 %0, %1;" : "=f"(r) : "f"(v));
    return r;
}

// column permutation: within each 8-col group, cols c and c+4 sit adjacent
// slot(c) = (c>>3)*8 + (c&3)*2 + ((c&7)>>2)
__device__ __forceinline__ int slotc(int c) {
    return ((c >> 3) << 3) + ((c & 3) << 1) + ((c & 7) >> 2);
}

__device__ __forceinline__ void mma_tf32(float c[4], const float a[4], const float b[2]) {
    const uint32_t* A = reinterpret_cast<const uint32_t*>(a);
    const uint32_t* B = reinterpret_cast<const uint32_t*>(b);
    asm volatile(
        "mma.sync.aligned.m16n8k8.row.col.f32.tf32.tf32.f32 "
        "{%0,%1,%2,%3}, {%4,%5,%6,%7}, {%8,%9}, {%0,%1,%2,%3};"
        : "+f"(c[0]), "+f"(c[1]), "+f"(c[2]), "+f"(c[3])
        : "r"(A[0]), "r"(A[1]), "r"(A[2]), "r"(A[3]), "r"(B[0]), "r"(B[1]));
}

extern "C" __global__ void __launch_bounds__(256, 1)
rnn_kernel(const float* __restrict__ x,
           const float* __restrict__ W_left, const float* __restrict__ W_right,
           const float* __restrict__ W_up,   const float* __restrict__ W_down,
           float* __restrict__ out)
{
    extern __shared__ float smem[];
    float* Xb = smem;               // [194][68] unrounded x, permuted cols
    float* P0 = Xb + BUFSZ;         // ping-pong state (tf32-rounded, permuted)
    float* P1 = P0 + BUFSZ;

    const int tid  = threadIdx.x;
    const int lane = tid & 31;
    const int warp = tid >> 5;
    const int mg   = warp & 3;      // 4 m-groups of 48 rows
    const int ng   = warp >> 2;     // 2 n-groups of 32 cols
    const int gID  = lane >> 2;     // 0..7
    const int tg   = lane & 3;      // 0..3
    const int s0_  = ((2 * tg) & 3) * 2 + ((2 * tg) >> 2);       // store slot for col 2tg
    const int s1_  = ((2 * tg + 1) & 3) * 2 + ((2 * tg + 1) >> 2); // store slot for col 2tg+1

    long inBase, outBase;
    int pixIn, pixOut, chBase;
    const float *Wfp, *Wbp;
    {
        int l = blockIdx.x;
        if (l < NLINES_H) {                       // horizontal row
            inBase  = (long)l * (192 * 64);
            outBase = (long)l * (192 * 256);
            pixIn   = 64;   pixOut = 256;  chBase = 0;
            Wfp = W_left;  Wbp = W_right;
        } else {                                   // vertical column
            int l2 = l - NLINES_H;
            int b = l2 / 192, w = l2 % 192;
            inBase  = (long)b * (192 * 192 * 64)  + (long)w * 64;
            outBase = (long)b * (192 * 192 * 256) + (long)w * 256;
            pixIn   = 192 * 64;  pixOut = 192 * 256;  chBase = 128;
            Wfp = W_up;  Wbp = W_down;
        }
    }
    const float* xl = x + inBase;
    float* ol = out + outBase;

    // ---- zero guard rows (rows 0 and 193 of all three buffers) ----
    if (tid < LSTR) {
        Xb[tid] = 0.f;  Xb[193 * LSTR + tid] = 0.f;
        P0[tid] = 0.f;  P0[193 * LSTR + tid] = 0.f;
        P1[tid] = 0.f;  P1[193 * LSTR + tid] = 0.f;
    }

    // ---- load x line into Xb (unrounded, permuted columns) ----
    for (int i = tid; i < LINE * 16; i += 256) {
        int p = i >> 4, q = (i & 15) << 2;
        float4 v = *reinterpret_cast<const float4*>(xl + (long)p * pixIn + q);
        float* row = &Xb[(p + 1) * LSTR];
        row[slotc(q)]     = v.x;
        row[slotc(q + 1)] = v.y;
        row[slotc(q + 2)] = v.z;
        row[slotc(q + 3)] = v.w;
    }
    __syncthreads();

    const int m0 = mg * 48;
    const int n0 = ng * 32;

    #pragma unroll 1
    for (int dir = 0; dir < 2; dir++) {
        const float* Wg  = dir ? Wbp : Wfp;
        const int shift  = dir ? 1 : -1;   // fwd reads p-1, bwd reads p+1

        // ---- hoist B fragments (tf32-rounded weights) into registers ----
        float b[8][4][2];
        #pragma unroll
        for (int kc = 0; kc < 8; kc++)
            #pragma unroll
            for (int nt = 0; nt < 4; nt++) {
                int kk = kc * 8 + tg;
                int nn = n0 + nt * 8 + gID;
                b[kc][nt][0] = tf32r(__ldg(&Wg[kk * 64 + nn]));
                b[kc][nt][1] = tf32r(__ldg(&Wg[(kk + 4) * 64 + nn]));
            }

        float acc[3][4][4];
        #pragma unroll
        for (int mt = 0; mt < 3; mt++)
            #pragma unroll
            for (int nt = 0; nt < 4; nt++)
                #pragma unroll
                for (int e = 0; e < 4; e++) acc[mt][nt][e] = 0.f;

        // base offsets
        int offA[3], offS[3];
        #pragma unroll
        for (int mt = 0; mt < 3; mt++) {
            offA[mt] = (m0 + mt * 16 + gID + shift + 1) * LSTR + 2 * tg;
            offS[mt] = (m0 + mt * 16 + gID + 1) * LSTR + n0;
        }

        const float* src = Xb;     // step 0 reads x (needs rounding)
        float* dst = P0;

        #pragma unroll 1
        for (int s = 0; s < RSTEPS; s++) {
            float Cf[3][4][4];
            #pragma unroll
            for (int mt = 0; mt < 3; mt++)
                #pragma unroll
                for (int nt = 0; nt < 4; nt++)
                    #pragma unroll
                    for (int e = 0; e < 4; e++) Cf[mt][nt][e] = 0.f;

            #pragma unroll
            for (int kc = 0; kc < 8; kc++) {
                float a[3][4];
                #pragma unroll
                for (int mt = 0; mt < 3; mt++) {
                    float2 lo = *reinterpret_cast<const float2*>(&src[offA[mt] + kc * 8]);
                    float2 hi = *reinterpret_cast<const float2*>(&src[offA[mt] + 8 * LSTR + kc * 8]);
                    if (s == 0) {   // x is unrounded in Xb
                        a[mt][0] = tf32r(lo.x); a[mt][1] = tf32r(hi.x);
                        a[mt][2] = tf32r(lo.y); a[mt][3] = tf32r(hi.y);
                    } else {        // state already tf32-rounded
                        a[mt][0] = lo.x; a[mt][1] = hi.x;
                        a[mt][2] = lo.y; a[mt][3] = hi.y;
                    }
                }
                #pragma unroll
                for (int mt = 0; mt < 3; mt++)
                    #pragma unroll
                    for (int nt = 0; nt < 4; nt++)
                        mma_tf32(Cf[mt][nt], a[mt], b[kc][nt]);
            }

            const bool last = (s == RSTEPS - 1);
            #pragma unroll
            for (int mt = 0; mt < 3; mt++) {
                #pragma unroll
                for (int nt = 0; nt < 4; nt++) {
                    float v0 = tf32r(fmaxf(Cf[mt][nt][0], 0.f));
                    float v1 = tf32r(fmaxf(Cf[mt][nt][1], 0.f));
                    float v2 = tf32r(fmaxf(Cf[mt][nt][2], 0.f));
                    float v3 = tf32r(fmaxf(Cf[mt][nt][3], 0.f));
                    acc[mt][nt][0] += v0;  acc[mt][nt][1] += v1;
                    acc[mt][nt][2] += v2;  acc[mt][nt][3] += v3;
                    if (!last) {
                        float* d0 = &dst[offS[mt] + nt * 8];
                        d0[s0_]            = v0;
                        d0[s1_]            = v1;
                        d0[8 * LSTR + s0_] = v2;
                        d0[8 * LSTR + s1_] = v3;
                    }
                }
            }

            if (!last) __syncthreads();

            // advance ping-pong: s0: Xb->P0; s1: P0->P1; s2: P1->P0; ...
            src = dst;
            dst = (dst == P0) ? P1 : P0;
        }

        // ---- epilogue: out = x + acc (x from Xb, exact fp32) ----
        const int cb = chBase + dir * 64;
        #pragma unroll
        for (int mt = 0; mt < 3; mt++) {
            int r = m0 + mt * 16 + gID;
            const float* xr0 = &Xb[(r + 1) * LSTR + n0];
            const float* xr1 = &Xb[(r + 9) * LSTR + n0];
            #pragma unroll
            for (int nt = 0; nt < 4; nt++) {
                int cc = n0 + nt * 8 + 2 * tg;
                float2 o0 = make_float2(xr0[nt * 8 + s0_] + acc[mt][nt][0],
                                        xr0[nt * 8 + s1_] + acc[mt][nt][1]);
                float2 o1 = make_float2(xr1[nt * 8 + s0_] + acc[mt][nt][2],
                                        xr1[nt * 8 + s1_] + acc[mt][nt][3]);
                *reinterpret_cast<float2*>(ol + (long)r       * pixOut + cb + cc) = o0;
                *reinterpret_cast<float2*>(ol + (long)(r + 8) * pixOut + cb + cc) = o1;
            }
        }

        // all P0/P1 & Xb reads of this direction must finish before dir 2
        __syncthreads();
    }
}

extern "C" void kernel_launch(void* const* d_in, const int* in_sizes, int n_in,
                              void* d_out, int out_size)
{
    const float* x  = (const float*)d_in[0];
    const float* wl = (const float*)d_in[1];
    const float* wr = (const float*)d_in[2];
    const float* wu = (const float*)d_in[3];
    const float* wd = (const float*)d_in[4];
    float* out = (float*)d_out;

    cudaFuncSetAttribute(rnn_kernel, cudaFuncAttributeMaxDynamicSharedMemorySize, SMEM_BYTES);
    rnn_kernel<<<3072, 256, SMEM_BYTES>>>(x, wl, wr, wu, wd, out);
}